// round 1
// baseline (speedup 1.0000x reference)
#include <cuda_runtime.h>

#define Tn 192
#define Hn 1024
#define NHn 16
#define HDn 64
#define H3n 3072

// Scratch (device globals — no allocation allowed)
__device__ float g_qkv[Tn * H3n];
__device__ float g_o[Tn * Hn];
__device__ float g_tmp[Tn * Hn];

// ---------------------------------------------------------------------------
__global__ void copy_kernel(const float* __restrict__ src, float* __restrict__ dst, int n) {
    int i = blockIdx.x * blockDim.x + threadIdx.x;
    if (i < n) dst[i] = src[i];
}

// ---------------------------------------------------------------------------
// C[M,N] = A[M,K] @ B[N,K]^T + bias[N]
// BM=BN=64, BK=16, 256 threads, 4x4 microtile per thread.
// M,N,K all multiples of tile sizes for this problem (192/3072/1024).
__global__ void gemm_nt_kernel(const float* __restrict__ A, const float* __restrict__ B,
                               const float* __restrict__ bias, float* __restrict__ C,
                               int M, int N, int K) {
    __shared__ float As[16][64];
    __shared__ float Bs[16][64];
    int tid = threadIdx.x;
    int bm = blockIdx.y * 64;
    int bn = blockIdx.x * 64;
    int tx = tid & 15;
    int ty = tid >> 4;
    int lr = tid >> 2;         // 0..63 tile row
    int lc = (tid & 3) * 4;    // 0,4,8,12 tile k-col

    float acc[4][4];
    #pragma unroll
    for (int i = 0; i < 4; i++)
        #pragma unroll
        for (int j = 0; j < 4; j++) acc[i][j] = 0.f;

    const float* Ap = A + (bm + lr) * K + lc;
    const float* Bp = B + (bn + lr) * K + lc;

    for (int k0 = 0; k0 < K; k0 += 16) {
        float4 a = *(const float4*)(Ap + k0);
        float4 b = *(const float4*)(Bp + k0);
        As[lc + 0][lr] = a.x; As[lc + 1][lr] = a.y;
        As[lc + 2][lr] = a.z; As[lc + 3][lr] = a.w;
        Bs[lc + 0][lr] = b.x; Bs[lc + 1][lr] = b.y;
        Bs[lc + 2][lr] = b.z; Bs[lc + 3][lr] = b.w;
        __syncthreads();
        #pragma unroll
        for (int kk = 0; kk < 16; kk++) {
            float av[4], bv[4];
            #pragma unroll
            for (int i = 0; i < 4; i++) av[i] = As[kk][ty * 4 + i];
            #pragma unroll
            for (int j = 0; j < 4; j++) bv[j] = Bs[kk][tx * 4 + j];
            #pragma unroll
            for (int i = 0; i < 4; i++)
                #pragma unroll
                for (int j = 0; j < 4; j++)
                    acc[i][j] += av[i] * bv[j];
        }
        __syncthreads();
    }

    #pragma unroll
    for (int i = 0; i < 4; i++) {
        int row = bm + ty * 4 + i;
        #pragma unroll
        for (int j = 0; j < 4; j++) {
            int col = bn + tx * 4 + j;
            C[row * N + col] = acc[i][j] + bias[col];
        }
    }
}

// ---------------------------------------------------------------------------
// Attention for one (query row, head) pair. 192 threads (one per key).
// NOTE: the reference's additive edge-weight bias is constant across keys
// (softmax over NE sums to 1 -> ew == 1/(T+1e-6) for every (q,k)), which is a
// softmax invariant, so it is omitted exactly.
__global__ void attn_kernel(const float* __restrict__ qkv, float* __restrict__ o) {
    int q = blockIdx.x;
    int h = blockIdx.y;
    int tid = threadIdx.x;  // 0..191

    __shared__ float qv[HDn];
    __shared__ float p[Tn];
    __shared__ float wred[6];

    if (tid < HDn) qv[tid] = qkv[q * H3n + h * HDn + tid];
    __syncthreads();

    const float* krow = qkv + tid * H3n + Hn + h * HDn;
    float s = 0.f;
    #pragma unroll
    for (int d = 0; d < HDn; d++) s += qv[d] * krow[d];
    s *= 0.125f;  // 1/sqrt(64)

    // block max
    float m = s;
    #pragma unroll
    for (int off = 16; off > 0; off >>= 1)
        m = fmaxf(m, __shfl_xor_sync(0xffffffffu, m, off));
    if ((tid & 31) == 0) wred[tid >> 5] = m;
    __syncthreads();
    float bmax = wred[0];
    #pragma unroll
    for (int w = 1; w < 6; w++) bmax = fmaxf(bmax, wred[w]);

    float e = expf(s - bmax);
    p[tid] = e;
    float su = e;
    #pragma unroll
    for (int off = 16; off > 0; off >>= 1)
        su += __shfl_xor_sync(0xffffffffu, su, off);
    __syncthreads();  // protect wred reuse + ensure p[] visible
    if ((tid & 31) == 0) wred[tid >> 5] = su;
    __syncthreads();
    float bsum = 0.f;
    #pragma unroll
    for (int w = 0; w < 6; w++) bsum += wred[w];
    float inv = 1.f / bsum;

    if (tid < HDn) {
        float acc = 0.f;
        const float* vbase = qkv + 2 * Hn + h * HDn + tid;
        #pragma unroll 4
        for (int sI = 0; sI < Tn; sI++) acc += p[sI] * vbase[sI * H3n];
        o[q * Hn + h * HDn + tid] = acc * inv;
    }
}

// ---------------------------------------------------------------------------
// x[t,:] += LN(y[t,:]) * g + b        (LN over H=1024, eps=1e-5)
// 256 threads, 4 elements each.
__global__ void ln_residual_kernel(const float* __restrict__ y,
                                   const float* __restrict__ g,
                                   const float* __restrict__ b,
                                   float* __restrict__ x) {
    int t = blockIdx.x;
    int tid = threadIdx.x;  // 0..255
    const float* row = y + t * Hn;
    float4 v = *(const float4*)(row + tid * 4);
    float sum = v.x + v.y + v.z + v.w;
    float sq = v.x * v.x + v.y * v.y + v.z * v.z + v.w * v.w;

    __shared__ float s1[8], s2[8];
    #pragma unroll
    for (int off = 16; off > 0; off >>= 1) {
        sum += __shfl_xor_sync(0xffffffffu, sum, off);
        sq  += __shfl_xor_sync(0xffffffffu, sq, off);
    }
    if ((tid & 31) == 0) { s1[tid >> 5] = sum; s2[tid >> 5] = sq; }
    __syncthreads();
    float ts = 0.f, tq = 0.f;
    #pragma unroll
    for (int w = 0; w < 8; w++) { ts += s1[w]; tq += s2[w]; }

    float mean = ts * (1.f / Hn);
    float var = tq * (1.f / Hn) - mean * mean;
    float r = rsqrtf(var + 1e-5f);

    float4 go = *(const float4*)(g + tid * 4);
    float4 bo = *(const float4*)(b + tid * 4);
    float4 xo = *(const float4*)(x + t * Hn + tid * 4);
    xo.x += (v.x - mean) * r * go.x + bo.x;
    xo.y += (v.y - mean) * r * go.y + bo.y;
    xo.z += (v.z - mean) * r * go.z + bo.z;
    xo.w += (v.w - mean) * r * go.w + bo.w;
    *(float4*)(x + t * Hn + tid * 4) = xo;
}

// ---------------------------------------------------------------------------
extern "C" void kernel_launch(void* const* d_in, const int* in_sizes, int n_in,
                              void* d_out, int out_size) {
    const float* nodes     = (const float*)d_in[0];
    const float* mha_in_w  = (const float*)d_in[14];  // [2,3072,1024]
    const float* mha_in_b  = (const float*)d_in[15];  // [2,3072]
    const float* mha_out_w = (const float*)d_in[16];  // [2,1024,1024]
    const float* mha_out_b = (const float*)d_in[17];  // [2,1024]
    const float* mha_ln_g  = (const float*)d_in[18];  // [2,1024]
    const float* mha_ln_b  = (const float*)d_in[19];  // [2,1024]
    float* x = (float*)d_out;                          // [192,1024] running state

    float *qkv, *o, *tmp;
    cudaGetSymbolAddress((void**)&qkv, g_qkv);
    cudaGetSymbolAddress((void**)&o,   g_o);
    cudaGetSymbolAddress((void**)&tmp, g_tmp);

    // x = nodes
    copy_kernel<<<(Tn * Hn + 255) / 256, 256>>>(nodes, x, Tn * Hn);

    for (int l = 0; l < 2; l++) {
        const float* Wi = mha_in_w  + (size_t)l * H3n * Hn;
        const float* bi = mha_in_b  + (size_t)l * H3n;
        const float* Wo = mha_out_w + (size_t)l * Hn * Hn;
        const float* bo = mha_out_b + (size_t)l * Hn;
        const float* lg = mha_ln_g  + (size_t)l * Hn;
        const float* lb = mha_ln_b  + (size_t)l * Hn;

        // qkv = x @ Wi^T + bi     [192, 3072]
        gemm_nt_kernel<<<dim3(H3n / 64, Tn / 64), 256>>>(x, Wi, bi, qkv, Tn, H3n, Hn);
        // attention -> o          [192, 1024]
        attn_kernel<<<dim3(Tn, NHn), Tn>>>(qkv, o);
        // tmp = o @ Wo^T + bo     [192, 1024]
        gemm_nt_kernel<<<dim3(Hn / 64, Tn / 64), 256>>>(o, Wo, bo, tmp, Tn, Hn, Hn);
        // x += LN(tmp)*g + b
        ln_residual_kernel<<<Tn, 256>>>(tmp, lg, lb, x);
    }
}

// round 2
// speedup vs baseline: 1.5599x; 1.5599x over previous
#include <cuda_runtime.h>
#include <cstdint>

#define Tn 192
#define Hn 1024
#define NHn 16
#define HDn 64
#define H3n 3072

// Scratch (device globals — no allocation allowed)
__device__ float g_qkv[Tn * H3n];
__device__ float g_o[Tn * Hn];
__device__ float g_tmp[Tn * Hn];

__device__ __forceinline__ uint32_t f2tf32(float f) {
    uint32_t u;
    asm("cvt.rna.tf32.f32 %0, %1;" : "=r"(u) : "f"(f));
    return u;
}

// ---------------------------------------------------------------------------
__global__ void copy_kernel(const float* __restrict__ src, float* __restrict__ dst, int n) {
    int i = blockIdx.x * blockDim.x + threadIdx.x;
    if (i < n) dst[i] = src[i];
}

// ---------------------------------------------------------------------------
// C[M,N] = A[M,K] @ B[N,K]^T + bias[N], TF32 tensor-core path.
// Block tile 64x64, BK=32, 128 threads = 4 warps in 2x2; 32x32 per warp via
// mma.sync.aligned.m16n8k8.row.col.f32.tf32.tf32.f32 (2 m-tiles x 4 n-tiles).
// M % 64 == 0, N % 64 == 0, K % 32 == 0 hold for all uses here.
__global__ void gemm_tf32_kernel(const float* __restrict__ A, const float* __restrict__ B,
                                 const float* __restrict__ bias, float* __restrict__ C,
                                 int M, int N, int K) {
    __shared__ uint32_t As[64][33];  // [m][k], pad to dodge bank conflicts
    __shared__ uint32_t Bs[64][33];  // [n][k]

    const int tid = threadIdx.x;
    const int wid = tid >> 5;
    const int lane = tid & 31;
    const int g = lane >> 2;   // group 0..7
    const int t = lane & 3;    // thread-in-group 0..3

    const int bm = blockIdx.y * 64;
    const int bn = blockIdx.x * 64;
    const int wm = (wid >> 1) * 32;  // warp m offset in tile
    const int wn = (wid & 1) * 32;   // warp n offset in tile

    float acc[2][4][4];
    #pragma unroll
    for (int mi = 0; mi < 2; mi++)
        #pragma unroll
        for (int ni = 0; ni < 4; ni++)
            #pragma unroll
            for (int r = 0; r < 4; r++) acc[mi][ni][r] = 0.f;

    // global->smem mapping: each thread loads 4 float4 per tile (64x32 floats)
    const int ldr = tid >> 3;        // 0..15
    const int ldc = (tid & 7) * 4;   // 0,4,...,28

    for (int k0 = 0; k0 < K; k0 += 32) {
        #pragma unroll
        for (int i = 0; i < 4; i++) {
            int r = ldr + i * 16;
            float4 a = *(const float4*)(A + (size_t)(bm + r) * K + k0 + ldc);
            As[r][ldc + 0] = f2tf32(a.x);
            As[r][ldc + 1] = f2tf32(a.y);
            As[r][ldc + 2] = f2tf32(a.z);
            As[r][ldc + 3] = f2tf32(a.w);
            float4 b = *(const float4*)(B + (size_t)(bn + r) * K + k0 + ldc);
            Bs[r][ldc + 0] = f2tf32(b.x);
            Bs[r][ldc + 1] = f2tf32(b.y);
            Bs[r][ldc + 2] = f2tf32(b.z);
            Bs[r][ldc + 3] = f2tf32(b.w);
        }
        __syncthreads();

        #pragma unroll
        for (int ks = 0; ks < 4; ks++) {
            const int kb = ks * 8;
            uint32_t af[2][4];
            #pragma unroll
            for (int mi = 0; mi < 2; mi++) {
                int r0 = wm + mi * 16 + g;
                af[mi][0] = As[r0][kb + t];
                af[mi][1] = As[r0 + 8][kb + t];
                af[mi][2] = As[r0][kb + t + 4];
                af[mi][3] = As[r0 + 8][kb + t + 4];
            }
            uint32_t bf[4][2];
            #pragma unroll
            for (int ni = 0; ni < 4; ni++) {
                int n0 = wn + ni * 8 + g;
                bf[ni][0] = Bs[n0][kb + t];
                bf[ni][1] = Bs[n0][kb + t + 4];
            }
            #pragma unroll
            for (int mi = 0; mi < 2; mi++)
                #pragma unroll
                for (int ni = 0; ni < 4; ni++) {
                    asm volatile(
                        "mma.sync.aligned.m16n8k8.row.col.f32.tf32.tf32.f32 "
                        "{%0,%1,%2,%3}, {%4,%5,%6,%7}, {%8,%9}, {%0,%1,%2,%3};"
                        : "+f"(acc[mi][ni][0]), "+f"(acc[mi][ni][1]),
                          "+f"(acc[mi][ni][2]), "+f"(acc[mi][ni][3])
                        : "r"(af[mi][0]), "r"(af[mi][1]), "r"(af[mi][2]), "r"(af[mi][3]),
                          "r"(bf[ni][0]), "r"(bf[ni][1]));
                }
        }
        __syncthreads();
    }

    // epilogue: c0:(g,2t) c1:(g,2t+1) c2:(g+8,2t) c3:(g+8,2t+1)
    #pragma unroll
    for (int mi = 0; mi < 2; mi++) {
        #pragma unroll
        for (int ni = 0; ni < 4; ni++) {
            int row0 = bm + wm + mi * 16 + g;
            int col0 = bn + wn + ni * 8 + 2 * t;
            C[(size_t)row0 * N + col0]            = acc[mi][ni][0] + bias[col0];
            C[(size_t)row0 * N + col0 + 1]        = acc[mi][ni][1] + bias[col0 + 1];
            C[(size_t)(row0 + 8) * N + col0]      = acc[mi][ni][2] + bias[col0];
            C[(size_t)(row0 + 8) * N + col0 + 1]  = acc[mi][ni][3] + bias[col0 + 1];
        }
    }
}

// ---------------------------------------------------------------------------
// Attention for one (query row, head) pair. 192 threads.
// The reference's additive edge-weight bias is constant across keys (softmax
// over NE sums to 1), a softmax invariant — omitted exactly.
__global__ void attn_kernel(const float* __restrict__ qkv, float* __restrict__ o) {
    int q = blockIdx.x;
    int h = blockIdx.y;
    int tid = threadIdx.x;  // 0..191

    __shared__ __align__(16) float qv[HDn];
    __shared__ float p[Tn];
    __shared__ float wred[6];
    __shared__ float part[3][HDn];

    if (tid < HDn) qv[tid] = qkv[q * H3n + h * HDn + tid];
    __syncthreads();

    // scores: thread tid handles key row tid
    const float4* kr = (const float4*)(qkv + (size_t)tid * H3n + Hn + h * HDn);
    const float4* qf = (const float4*)qv;
    float s = 0.f;
    #pragma unroll
    for (int i = 0; i < HDn / 4; i++) {
        float4 kv = kr[i];
        float4 qq = qf[i];
        s += qq.x * kv.x + qq.y * kv.y + qq.z * kv.z + qq.w * kv.w;
    }
    s *= 0.125f;  // 1/sqrt(64)

    // block max
    float m = s;
    #pragma unroll
    for (int off = 16; off > 0; off >>= 1)
        m = fmaxf(m, __shfl_xor_sync(0xffffffffu, m, off));
    if ((tid & 31) == 0) wred[tid >> 5] = m;
    __syncthreads();
    float bmax = wred[0];
    #pragma unroll
    for (int w = 1; w < 6; w++) bmax = fmaxf(bmax, wred[w]);

    float e = expf(s - bmax);
    p[tid] = e;
    float su = e;
    #pragma unroll
    for (int off = 16; off > 0; off >>= 1)
        su += __shfl_xor_sync(0xffffffffu, su, off);
    __syncthreads();  // protect wred reuse + publish p[]
    if ((tid & 31) == 0) wred[tid >> 5] = su;
    __syncthreads();
    float bsum = 0.f;
    #pragma unroll
    for (int w = 0; w < 6; w++) bsum += wred[w];
    float inv = 1.f / bsum;

    // P @ V: thread = (d, chunk), 3 chunks of 64 keys
    int d = tid & 63;
    int c = tid >> 6;  // 0..2
    const float* vb = qkv + 2 * Hn + h * HDn + d + (size_t)(c * 64) * H3n;
    float acc = 0.f;
    #pragma unroll 8
    for (int sI = 0; sI < 64; sI++) acc += p[c * 64 + sI] * vb[(size_t)sI * H3n];
    part[c][d] = acc;
    __syncthreads();
    if (tid < HDn)
        o[(size_t)q * Hn + h * HDn + tid] =
            (part[0][tid] + part[1][tid] + part[2][tid]) * inv;
}

// ---------------------------------------------------------------------------
// x[t,:] += LN(y[t,:]) * g + b        (LN over H=1024, eps=1e-5)
__global__ void ln_residual_kernel(const float* __restrict__ y,
                                   const float* __restrict__ g,
                                   const float* __restrict__ b,
                                   float* __restrict__ x) {
    int t = blockIdx.x;
    int tid = threadIdx.x;  // 0..255
    const float* row = y + (size_t)t * Hn;
    float4 v = *(const float4*)(row + tid * 4);
    float sum = v.x + v.y + v.z + v.w;
    float sq = v.x * v.x + v.y * v.y + v.z * v.z + v.w * v.w;

    __shared__ float s1[8], s2[8];
    #pragma unroll
    for (int off = 16; off > 0; off >>= 1) {
        sum += __shfl_xor_sync(0xffffffffu, sum, off);
        sq  += __shfl_xor_sync(0xffffffffu, sq, off);
    }
    if ((tid & 31) == 0) { s1[tid >> 5] = sum; s2[tid >> 5] = sq; }
    __syncthreads();
    float ts = 0.f, tq = 0.f;
    #pragma unroll
    for (int w = 0; w < 8; w++) { ts += s1[w]; tq += s2[w]; }

    float mean = ts * (1.f / Hn);
    float var = tq * (1.f / Hn) - mean * mean;
    float r = rsqrtf(var + 1e-5f);

    float4 go = *(const float4*)(g + tid * 4);
    float4 bo = *(const float4*)(b + tid * 4);
    float4 xo = *(const float4*)(x + (size_t)t * Hn + tid * 4);
    xo.x += (v.x - mean) * r * go.x + bo.x;
    xo.y += (v.y - mean) * r * go.y + bo.y;
    xo.z += (v.z - mean) * r * go.z + bo.z;
    xo.w += (v.w - mean) * r * go.w + bo.w;
    *(float4*)(x + (size_t)t * Hn + tid * 4) = xo;
}

// ---------------------------------------------------------------------------
extern "C" void kernel_launch(void* const* d_in, const int* in_sizes, int n_in,
                              void* d_out, int out_size) {
    const float* nodes     = (const float*)d_in[0];
    const float* mha_in_w  = (const float*)d_in[14];  // [2,3072,1024]
    const float* mha_in_b  = (const float*)d_in[15];  // [2,3072]
    const float* mha_out_w = (const float*)d_in[16];  // [2,1024,1024]
    const float* mha_out_b = (const float*)d_in[17];  // [2,1024]
    const float* mha_ln_g  = (const float*)d_in[18];  // [2,1024]
    const float* mha_ln_b  = (const float*)d_in[19];  // [2,1024]
    float* x = (float*)d_out;                          // [192,1024] running state

    float *qkv, *o, *tmp;
    cudaGetSymbolAddress((void**)&qkv, g_qkv);
    cudaGetSymbolAddress((void**)&o,   g_o);
    cudaGetSymbolAddress((void**)&tmp, g_tmp);

    // x = nodes
    copy_kernel<<<(Tn * Hn + 255) / 256, 256>>>(nodes, x, Tn * Hn);

    for (int l = 0; l < 2; l++) {
        const float* Wi = mha_in_w  + (size_t)l * H3n * Hn;
        const float* bi = mha_in_b  + (size_t)l * H3n;
        const float* Wo = mha_out_w + (size_t)l * Hn * Hn;
        const float* bo = mha_out_b + (size_t)l * Hn;
        const float* lg = mha_ln_g  + (size_t)l * Hn;
        const float* lb = mha_ln_b  + (size_t)l * Hn;

        // qkv = x @ Wi^T + bi     [192, 3072]
        gemm_tf32_kernel<<<dim3(H3n / 64, Tn / 64), 128>>>(x, Wi, bi, qkv, Tn, H3n, Hn);
        // attention -> o          [192, 1024]
        attn_kernel<<<dim3(Tn, NHn), Tn>>>(qkv, o);
        // tmp = o @ Wo^T + bo     [192, 1024]
        gemm_tf32_kernel<<<dim3(Hn / 64, Tn / 64), 128>>>(o, Wo, bo, tmp, Tn, Hn, Hn);
        // x += LN(tmp)*g + b
        ln_residual_kernel<<<Tn, 256>>>(tmp, lg, lb, x);
    }
}

// round 3
// speedup vs baseline: 2.9077x; 1.8640x over previous
#include <cuda_runtime.h>
#include <cstdint>

#define Tn 192
#define Hn 1024
#define NHn 16
#define HDn 64
#define H3n 3072

// Scratch (device globals — no allocation allowed)
__device__ float g_qkv[Tn * H3n];
__device__ float g_o[Tn * Hn];
__device__ float g_tmp[Tn * Hn];
__device__ float g_part[2 * Tn * H3n];  // split-K partials (max: sk=2 on 192x3072)

__device__ __forceinline__ uint32_t f2tf32(float f) {
    uint32_t u;
    asm("cvt.rna.tf32.f32 %0, %1;" : "=r"(u) : "f"(f));
    return u;
}

// ---------------------------------------------------------------------------
__global__ void copy_kernel(const float* __restrict__ src, float* __restrict__ dst, int n) {
    int i = blockIdx.x * blockDim.x + threadIdx.x;
    if (i < n) dst[i] = src[i];
}

// ---------------------------------------------------------------------------
// Split-K TF32 GEMM: P[z] = A[M,Kslice] @ B[N,Kslice]^T  for k-slice z.
// Block tile 64x64, BK=32, 128 threads, warp tile 32x32 (2x2 warps).
// Double-buffered smem + register prefetch of the next k-chunk.
__global__ void gemm_tf32_splitk(const float* __restrict__ A, const float* __restrict__ B,
                                 float* __restrict__ P, int M, int N, int K, int kps) {
    __shared__ uint32_t As[2][64][33];
    __shared__ uint32_t Bs[2][64][33];

    const int tid = threadIdx.x;
    const int wid = tid >> 5;
    const int lane = tid & 31;
    const int g = lane >> 2;
    const int t = lane & 3;

    const int bm = blockIdx.y * 64;
    const int bn = blockIdx.x * 64;
    const int wm = (wid >> 1) * 32;
    const int wn = (wid & 1) * 32;

    const int kbeg = blockIdx.z * kps;
    const int kend = kbeg + kps;

    float acc[2][4][4];
    #pragma unroll
    for (int mi = 0; mi < 2; mi++)
        #pragma unroll
        for (int ni = 0; ni < 4; ni++)
            #pragma unroll
            for (int r = 0; r < 4; r++) acc[mi][ni][r] = 0.f;

    const int ldr = tid >> 3;        // 0..15
    const int ldc = (tid & 7) * 4;   // 0,4,...,28

    float4 pa[4], pb[4];
    #pragma unroll
    for (int i = 0; i < 4; i++) {
        int r = ldr + i * 16;
        pa[i] = *(const float4*)(A + (size_t)(bm + r) * K + kbeg + ldc);
        pb[i] = *(const float4*)(B + (size_t)(bn + r) * K + kbeg + ldc);
    }

    int buf = 0;
    #pragma unroll
    for (int i = 0; i < 4; i++) {
        int r = ldr + i * 16;
        As[0][r][ldc + 0] = f2tf32(pa[i].x); As[0][r][ldc + 1] = f2tf32(pa[i].y);
        As[0][r][ldc + 2] = f2tf32(pa[i].z); As[0][r][ldc + 3] = f2tf32(pa[i].w);
        Bs[0][r][ldc + 0] = f2tf32(pb[i].x); Bs[0][r][ldc + 1] = f2tf32(pb[i].y);
        Bs[0][r][ldc + 2] = f2tf32(pb[i].z); Bs[0][r][ldc + 3] = f2tf32(pb[i].w);
    }
    __syncthreads();

    for (int k0 = kbeg; k0 < kend; k0 += 32) {
        const bool has_next = (k0 + 32) < kend;
        if (has_next) {
            #pragma unroll
            for (int i = 0; i < 4; i++) {
                int r = ldr + i * 16;
                pa[i] = *(const float4*)(A + (size_t)(bm + r) * K + k0 + 32 + ldc);
                pb[i] = *(const float4*)(B + (size_t)(bn + r) * K + k0 + 32 + ldc);
            }
        }

        #pragma unroll
        for (int ks = 0; ks < 4; ks++) {
            const int kb = ks * 8;
            uint32_t af[2][4];
            #pragma unroll
            for (int mi = 0; mi < 2; mi++) {
                int r0 = wm + mi * 16 + g;
                af[mi][0] = As[buf][r0][kb + t];
                af[mi][1] = As[buf][r0 + 8][kb + t];
                af[mi][2] = As[buf][r0][kb + t + 4];
                af[mi][3] = As[buf][r0 + 8][kb + t + 4];
            }
            uint32_t bf[4][2];
            #pragma unroll
            for (int ni = 0; ni < 4; ni++) {
                int n0 = wn + ni * 8 + g;
                bf[ni][0] = Bs[buf][n0][kb + t];
                bf[ni][1] = Bs[buf][n0][kb + t + 4];
            }
            #pragma unroll
            for (int mi = 0; mi < 2; mi++)
                #pragma unroll
                for (int ni = 0; ni < 4; ni++) {
                    asm volatile(
                        "mma.sync.aligned.m16n8k8.row.col.f32.tf32.tf32.f32 "
                        "{%0,%1,%2,%3}, {%4,%5,%6,%7}, {%8,%9}, {%0,%1,%2,%3};"
                        : "+f"(acc[mi][ni][0]), "+f"(acc[mi][ni][1]),
                          "+f"(acc[mi][ni][2]), "+f"(acc[mi][ni][3])
                        : "r"(af[mi][0]), "r"(af[mi][1]), "r"(af[mi][2]), "r"(af[mi][3]),
                          "r"(bf[ni][0]), "r"(bf[ni][1]));
                }
        }

        if (has_next) {
            int nb = buf ^ 1;
            #pragma unroll
            for (int i = 0; i < 4; i++) {
                int r = ldr + i * 16;
                As[nb][r][ldc + 0] = f2tf32(pa[i].x); As[nb][r][ldc + 1] = f2tf32(pa[i].y);
                As[nb][r][ldc + 2] = f2tf32(pa[i].z); As[nb][r][ldc + 3] = f2tf32(pa[i].w);
                Bs[nb][r][ldc + 0] = f2tf32(pb[i].x); Bs[nb][r][ldc + 1] = f2tf32(pb[i].y);
                Bs[nb][r][ldc + 2] = f2tf32(pb[i].z); Bs[nb][r][ldc + 3] = f2tf32(pb[i].w);
            }
            __syncthreads();
            buf = nb;
        }
    }

    float* Pz = P + (size_t)blockIdx.z * M * N;
    #pragma unroll
    for (int mi = 0; mi < 2; mi++) {
        #pragma unroll
        for (int ni = 0; ni < 4; ni++) {
            int row0 = bm + wm + mi * 16 + g;
            int col0 = bn + wn + ni * 8 + 2 * t;
            Pz[(size_t)row0 * N + col0]           = acc[mi][ni][0];
            Pz[(size_t)row0 * N + col0 + 1]       = acc[mi][ni][1];
            Pz[(size_t)(row0 + 8) * N + col0]     = acc[mi][ni][2];
            Pz[(size_t)(row0 + 8) * N + col0 + 1] = acc[mi][ni][3];
        }
    }
}

// ---------------------------------------------------------------------------
// C = sum_z P[z] + bias (broadcast over rows). float4-vectorized.
__global__ void reduce_bias_kernel(const float* __restrict__ P, const float* __restrict__ bias,
                                   float* __restrict__ C, int MN, int N, int sk) {
    int i = (blockIdx.x * blockDim.x + threadIdx.x) * 4;
    if (i >= MN) return;
    float4 s = *(const float4*)(P + i);
    for (int z = 1; z < sk; z++) {
        float4 p = *(const float4*)(P + (size_t)z * MN + i);
        s.x += p.x; s.y += p.y; s.z += p.z; s.w += p.w;
    }
    int n = i % N;
    float4 b = *(const float4*)(bias + n);
    s.x += b.x; s.y += b.y; s.z += b.z; s.w += b.w;
    *(float4*)(C + i) = s;
}

// ---------------------------------------------------------------------------
// Attention for one (query row, head) pair. 192 threads.
// Reference's additive edge bias is constant across keys (softmax over NE
// sums to 1) — a softmax invariant, omitted exactly.
__global__ void attn_kernel(const float* __restrict__ qkv, float* __restrict__ o) {
    int q = blockIdx.x;
    int h = blockIdx.y;
    int tid = threadIdx.x;  // 0..191

    __shared__ __align__(16) float qv[HDn];
    __shared__ float p[Tn];
    __shared__ float wred[6];
    __shared__ float part[3][HDn];

    if (tid < HDn) qv[tid] = qkv[q * H3n + h * HDn + tid];
    __syncthreads();

    const float4* kr = (const float4*)(qkv + (size_t)tid * H3n + Hn + h * HDn);
    const float4* qf = (const float4*)qv;
    float s = 0.f;
    #pragma unroll
    for (int i = 0; i < HDn / 4; i++) {
        float4 kv = kr[i];
        float4 qq = qf[i];
        s += qq.x * kv.x + qq.y * kv.y + qq.z * kv.z + qq.w * kv.w;
    }
    s *= 0.125f;

    float m = s;
    #pragma unroll
    for (int off = 16; off > 0; off >>= 1)
        m = fmaxf(m, __shfl_xor_sync(0xffffffffu, m, off));
    if ((tid & 31) == 0) wred[tid >> 5] = m;
    __syncthreads();
    float bmax = wred[0];
    #pragma unroll
    for (int w = 1; w < 6; w++) bmax = fmaxf(bmax, wred[w]);

    float e = expf(s - bmax);
    p[tid] = e;
    float su = e;
    #pragma unroll
    for (int off = 16; off > 0; off >>= 1)
        su += __shfl_xor_sync(0xffffffffu, su, off);
    __syncthreads();
    if ((tid & 31) == 0) wred[tid >> 5] = su;
    __syncthreads();
    float bsum = 0.f;
    #pragma unroll
    for (int w = 0; w < 6; w++) bsum += wred[w];
    float inv = 1.f / bsum;

    int d = tid & 63;
    int c = tid >> 6;
    const float* vb = qkv + 2 * Hn + h * HDn + d + (size_t)(c * 64) * H3n;
    float acc = 0.f;
    #pragma unroll 8
    for (int sI = 0; sI < 64; sI++) acc += p[c * 64 + sI] * vb[(size_t)sI * H3n];
    part[c][d] = acc;
    __syncthreads();
    if (tid < HDn)
        o[(size_t)q * Hn + h * HDn + tid] =
            (part[0][tid] + part[1][tid] + part[2][tid]) * inv;
}

// ---------------------------------------------------------------------------
__global__ void ln_residual_kernel(const float* __restrict__ y,
                                   const float* __restrict__ g,
                                   const float* __restrict__ b,
                                   float* __restrict__ x) {
    int t = blockIdx.x;
    int tid = threadIdx.x;
    const float* row = y + (size_t)t * Hn;
    float4 v = *(const float4*)(row + tid * 4);
    float sum = v.x + v.y + v.z + v.w;
    float sq = v.x * v.x + v.y * v.y + v.z * v.z + v.w * v.w;

    __shared__ float s1[8], s2[8];
    #pragma unroll
    for (int off = 16; off > 0; off >>= 1) {
        sum += __shfl_xor_sync(0xffffffffu, sum, off);
        sq  += __shfl_xor_sync(0xffffffffu, sq, off);
    }
    if ((tid & 31) == 0) { s1[tid >> 5] = sum; s2[tid >> 5] = sq; }
    __syncthreads();
    float ts = 0.f, tq = 0.f;
    #pragma unroll
    for (int w = 0; w < 8; w++) { ts += s1[w]; tq += s2[w]; }

    float mean = ts * (1.f / Hn);
    float var = tq * (1.f / Hn) - mean * mean;
    float r = rsqrtf(var + 1e-5f);

    float4 go = *(const float4*)(g + tid * 4);
    float4 bo = *(const float4*)(b + tid * 4);
    float4 xo = *(const float4*)(x + (size_t)t * Hn + tid * 4);
    xo.x += (v.x - mean) * r * go.x + bo.x;
    xo.y += (v.y - mean) * r * go.y + bo.y;
    xo.z += (v.z - mean) * r * go.z + bo.z;
    xo.w += (v.w - mean) * r * go.w + bo.w;
    *(float4*)(x + (size_t)t * Hn + tid * 4) = xo;
}

// ---------------------------------------------------------------------------
extern "C" void kernel_launch(void* const* d_in, const int* in_sizes, int n_in,
                              void* d_out, int out_size) {
    const float* nodes     = (const float*)d_in[0];
    const float* mha_in_w  = (const float*)d_in[14];
    const float* mha_in_b  = (const float*)d_in[15];
    const float* mha_out_w = (const float*)d_in[16];
    const float* mha_out_b = (const float*)d_in[17];
    const float* mha_ln_g  = (const float*)d_in[18];
    const float* mha_ln_b  = (const float*)d_in[19];
    float* x = (float*)d_out;

    float *qkv, *o, *tmp, *part;
    cudaGetSymbolAddress((void**)&qkv,  g_qkv);
    cudaGetSymbolAddress((void**)&o,    g_o);
    cudaGetSymbolAddress((void**)&tmp,  g_tmp);
    cudaGetSymbolAddress((void**)&part, g_part);

    copy_kernel<<<(Tn * Hn + 255) / 256, 256>>>(nodes, x, Tn * Hn);

    for (int l = 0; l < 2; l++) {
        const float* Wi = mha_in_w  + (size_t)l * H3n * Hn;
        const float* bi = mha_in_b  + (size_t)l * H3n;
        const float* Wo = mha_out_w + (size_t)l * Hn * Hn;
        const float* bo = mha_out_b + (size_t)l * Hn;
        const float* lg = mha_ln_g  + (size_t)l * Hn;
        const float* lb = mha_ln_b  + (size_t)l * Hn;

        // qkv = x @ Wi^T + bi  : split-K=2, grid 48x3x2 = 288 blocks
        gemm_tf32_splitk<<<dim3(H3n / 64, Tn / 64, 2), 128>>>(x, Wi, part, Tn, H3n, Hn, Hn / 2);
        reduce_bias_kernel<<<(Tn * H3n / 4 + 255) / 256, 256>>>(part, bi, qkv, Tn * H3n, H3n, 2);

        attn_kernel<<<dim3(Tn, NHn), Tn>>>(qkv, o);

        // tmp = o @ Wo^T + bo  : split-K=4, grid 16x3x4 = 192 blocks
        gemm_tf32_splitk<<<dim3(Hn / 64, Tn / 64, 4), 128>>>(o, Wo, part, Tn, Hn, Hn, Hn / 4);
        reduce_bias_kernel<<<(Tn * Hn / 4 + 255) / 256, 256>>>(part, bo, tmp, Tn * Hn, Hn, 4);

        ln_residual_kernel<<<Tn, 256>>>(tmp, lg, lb, x);
    }
}

// round 4
// speedup vs baseline: 4.1505x; 1.4274x over previous
#include <cuda_runtime.h>
#include <cstdint>

#define Tn 192
#define Hn 1024
#define NHn 16
#define HDn 64
#define H3n 3072

#define KP 68    // smem row stride (floats) for Q/K tiles
#define PP 196   // smem row stride for score matrix P
#define ATTN_SMEM_BYTES ((32*KP + 192*KP + 192*64 + 32*PP + 32) * 4)

// Scratch (device globals — no allocation allowed)
__device__ __align__(16) float g_qkv[Tn * H3n];
__device__ __align__(16) float g_o[Tn * Hn];
__device__ __align__(16) float g_tmp[Tn * Hn];
__device__ __align__(16) float g_part[2 * Tn * H3n];  // split-K partials

__device__ __forceinline__ uint32_t f2tf32(float f) {
    uint32_t u;
    asm("cvt.rna.tf32.f32 %0, %1;" : "=r"(u) : "f"(f));
    return u;
}

// ---------------------------------------------------------------------------
__global__ void copy_kernel(const float* __restrict__ src, float* __restrict__ dst, int n) {
    int i = blockIdx.x * blockDim.x + threadIdx.x;
    if (i < n) dst[i] = src[i];
}

// ---------------------------------------------------------------------------
// Split-K TF32 GEMM: P[z] = A[M,Kslice] @ B[N,Kslice]^T  (validated round 3)
__global__ void gemm_tf32_splitk(const float* __restrict__ A, const float* __restrict__ B,
                                 float* __restrict__ P, int M, int N, int K, int kps) {
    __shared__ uint32_t As[2][64][33];
    __shared__ uint32_t Bs[2][64][33];

    const int tid = threadIdx.x;
    const int wid = tid >> 5;
    const int lane = tid & 31;
    const int g = lane >> 2;
    const int t = lane & 3;

    const int bm = blockIdx.y * 64;
    const int bn = blockIdx.x * 64;
    const int wm = (wid >> 1) * 32;
    const int wn = (wid & 1) * 32;

    const int kbeg = blockIdx.z * kps;
    const int kend = kbeg + kps;

    float acc[2][4][4];
    #pragma unroll
    for (int mi = 0; mi < 2; mi++)
        #pragma unroll
        for (int ni = 0; ni < 4; ni++)
            #pragma unroll
            for (int r = 0; r < 4; r++) acc[mi][ni][r] = 0.f;

    const int ldr = tid >> 3;
    const int ldc = (tid & 7) * 4;

    float4 pa[4], pb[4];
    #pragma unroll
    for (int i = 0; i < 4; i++) {
        int r = ldr + i * 16;
        pa[i] = *(const float4*)(A + (size_t)(bm + r) * K + kbeg + ldc);
        pb[i] = *(const float4*)(B + (size_t)(bn + r) * K + kbeg + ldc);
    }

    int buf = 0;
    #pragma unroll
    for (int i = 0; i < 4; i++) {
        int r = ldr + i * 16;
        As[0][r][ldc + 0] = f2tf32(pa[i].x); As[0][r][ldc + 1] = f2tf32(pa[i].y);
        As[0][r][ldc + 2] = f2tf32(pa[i].z); As[0][r][ldc + 3] = f2tf32(pa[i].w);
        Bs[0][r][ldc + 0] = f2tf32(pb[i].x); Bs[0][r][ldc + 1] = f2tf32(pb[i].y);
        Bs[0][r][ldc + 2] = f2tf32(pb[i].z); Bs[0][r][ldc + 3] = f2tf32(pb[i].w);
    }
    __syncthreads();

    for (int k0 = kbeg; k0 < kend; k0 += 32) {
        const bool has_next = (k0 + 32) < kend;
        if (has_next) {
            #pragma unroll
            for (int i = 0; i < 4; i++) {
                int r = ldr + i * 16;
                pa[i] = *(const float4*)(A + (size_t)(bm + r) * K + k0 + 32 + ldc);
                pb[i] = *(const float4*)(B + (size_t)(bn + r) * K + k0 + 32 + ldc);
            }
        }

        #pragma unroll
        for (int ks = 0; ks < 4; ks++) {
            const int kb = ks * 8;
            uint32_t af[2][4];
            #pragma unroll
            for (int mi = 0; mi < 2; mi++) {
                int r0 = wm + mi * 16 + g;
                af[mi][0] = As[buf][r0][kb + t];
                af[mi][1] = As[buf][r0 + 8][kb + t];
                af[mi][2] = As[buf][r0][kb + t + 4];
                af[mi][3] = As[buf][r0 + 8][kb + t + 4];
            }
            uint32_t bf[4][2];
            #pragma unroll
            for (int ni = 0; ni < 4; ni++) {
                int n0 = wn + ni * 8 + g;
                bf[ni][0] = Bs[buf][n0][kb + t];
                bf[ni][1] = Bs[buf][n0][kb + t + 4];
            }
            #pragma unroll
            for (int mi = 0; mi < 2; mi++)
                #pragma unroll
                for (int ni = 0; ni < 4; ni++) {
                    asm volatile(
                        "mma.sync.aligned.m16n8k8.row.col.f32.tf32.tf32.f32 "
                        "{%0,%1,%2,%3}, {%4,%5,%6,%7}, {%8,%9}, {%0,%1,%2,%3};"
                        : "+f"(acc[mi][ni][0]), "+f"(acc[mi][ni][1]),
                          "+f"(acc[mi][ni][2]), "+f"(acc[mi][ni][3])
                        : "r"(af[mi][0]), "r"(af[mi][1]), "r"(af[mi][2]), "r"(af[mi][3]),
                          "r"(bf[ni][0]), "r"(bf[ni][1]));
                }
        }

        if (has_next) {
            int nb = buf ^ 1;
            #pragma unroll
            for (int i = 0; i < 4; i++) {
                int r = ldr + i * 16;
                As[nb][r][ldc + 0] = f2tf32(pa[i].x); As[nb][r][ldc + 1] = f2tf32(pa[i].y);
                As[nb][r][ldc + 2] = f2tf32(pa[i].z); As[nb][r][ldc + 3] = f2tf32(pa[i].w);
                Bs[nb][r][ldc + 0] = f2tf32(pb[i].x); Bs[nb][r][ldc + 1] = f2tf32(pb[i].y);
                Bs[nb][r][ldc + 2] = f2tf32(pb[i].z); Bs[nb][r][ldc + 3] = f2tf32(pb[i].w);
            }
            __syncthreads();
            buf = nb;
        }
    }

    float* Pz = P + (size_t)blockIdx.z * M * N;
    #pragma unroll
    for (int mi = 0; mi < 2; mi++) {
        #pragma unroll
        for (int ni = 0; ni < 4; ni++) {
            int row0 = bm + wm + mi * 16 + g;
            int col0 = bn + wn + ni * 8 + 2 * t;
            Pz[(size_t)row0 * N + col0]           = acc[mi][ni][0];
            Pz[(size_t)row0 * N + col0 + 1]       = acc[mi][ni][1];
            Pz[(size_t)(row0 + 8) * N + col0]     = acc[mi][ni][2];
            Pz[(size_t)(row0 + 8) * N + col0 + 1] = acc[mi][ni][3];
        }
    }
}

// ---------------------------------------------------------------------------
__global__ void reduce_bias_kernel(const float* __restrict__ P, const float* __restrict__ bias,
                                   float* __restrict__ C, int MN, int N, int sk) {
    int i = (blockIdx.x * blockDim.x + threadIdx.x) * 4;
    if (i >= MN) return;
    float4 s = *(const float4*)(P + i);
    for (int z = 1; z < sk; z++) {
        float4 p = *(const float4*)(P + (size_t)z * MN + i);
        s.x += p.x; s.y += p.y; s.z += p.z; s.w += p.w;
    }
    int n = i % N;
    float4 b = *(const float4*)(bias + n);
    s.x += b.x; s.y += b.y; s.z += b.z; s.w += b.w;
    *(float4*)(C + i) = s;
}

// ---------------------------------------------------------------------------
// Tiled attention: block = (32-query tile, head). 256 threads.
// Stages Q/K/V head-tiles in smem once; scores + softmax + PV all from smem.
// Reference's additive edge bias is constant across keys (softmax over NE
// sums to 1) — a softmax invariant, omitted exactly.
__global__ void attn_tiled_kernel(const float* __restrict__ qkv, float* __restrict__ o) {
    extern __shared__ float sm[];
    float* Qs  = sm;                    // [32][KP]
    float* Ks  = Qs + 32 * KP;          // [192][KP]
    float* Vs  = Ks + 192 * KP;         // [192][64]
    float* Pm  = Vs + 192 * 64;         // [32][PP]
    float* rin = Pm + 32 * PP;          // [32]

    const int qt = blockIdx.x;   // 0..5
    const int h  = blockIdx.y;   // 0..15
    const int t  = threadIdx.x;  // 0..255

    // ---- stage tiles ----
    #pragma unroll
    for (int i = t; i < 32 * 16; i += 256) {
        int r = i >> 4, c = (i & 15) * 4;
        *(float4*)&Qs[r * KP + c] =
            *(const float4*)&qkv[(size_t)(qt * 32 + r) * H3n + h * HDn + c];
    }
    #pragma unroll
    for (int i = t; i < 192 * 16; i += 256) {
        int r = i >> 4, c = (i & 15) * 4;
        *(float4*)&Ks[r * KP + c] =
            *(const float4*)&qkv[(size_t)r * H3n + Hn + h * HDn + c];
        *(float4*)&Vs[r * 64 + c] =
            *(const float4*)&qkv[(size_t)r * H3n + 2 * Hn + h * HDn + c];
    }
    __syncthreads();

    // ---- scores: thread = (q = t&31, key-group kg = t>>5 of 24 keys) ----
    {
        const int q = t & 31;
        const int kg = t >> 5;
        float s[24];
        #pragma unroll
        for (int j = 0; j < 24; j++) s[j] = 0.f;
        for (int d4 = 0; d4 < 16; d4++) {
            float4 qv = *(float4*)&Qs[q * KP + d4 * 4];
            #pragma unroll
            for (int j = 0; j < 24; j++) {
                float4 kv = *(float4*)&Ks[(kg * 24 + j) * KP + d4 * 4];
                s[j] += qv.x * kv.x + qv.y * kv.y + qv.z * kv.z + qv.w * kv.w;
            }
        }
        #pragma unroll
        for (int j = 0; j < 24; j++) Pm[q * PP + kg * 24 + j] = s[j] * 0.125f;
    }
    __syncthreads();

    // ---- softmax: warp w handles rows 4w..4w+3, lane-strided over 192 cols ----
    {
        const int w = t >> 5, lane = t & 31;
        for (int r = w * 4; r < w * 4 + 4; r++) {
            float v[6];
            float mx = -1e30f;
            #pragma unroll
            for (int i = 0; i < 6; i++) {
                v[i] = Pm[r * PP + lane + 32 * i];
                mx = fmaxf(mx, v[i]);
            }
            #pragma unroll
            for (int off = 16; off > 0; off >>= 1)
                mx = fmaxf(mx, __shfl_xor_sync(0xffffffffu, mx, off));
            float sum = 0.f;
            #pragma unroll
            for (int i = 0; i < 6; i++) {
                v[i] = expf(v[i] - mx);
                sum += v[i];
                Pm[r * PP + lane + 32 * i] = v[i];
            }
            #pragma unroll
            for (int off = 16; off > 0; off >>= 1)
                sum += __shfl_xor_sync(0xffffffffu, sum, off);
            if (lane == 0) rin[r] = 1.f / sum;
        }
    }
    __syncthreads();

    // ---- PV: thread = (q = t>>3, dim-group dg = t&7 of 8 dims) ----
    {
        const int q = t >> 3;
        const int dg = t & 7;
        float4 o0 = make_float4(0.f, 0.f, 0.f, 0.f);
        float4 o1 = make_float4(0.f, 0.f, 0.f, 0.f);
        for (int kc = 0; kc < 48; kc++) {
            float4 p4 = *(float4*)&Pm[q * PP + kc * 4];
            float pv[4] = {p4.x, p4.y, p4.z, p4.w};
            #pragma unroll
            for (int jj = 0; jj < 4; jj++) {
                int k = kc * 4 + jj;
                float4 va = *(float4*)&Vs[k * 64 + dg * 8];
                float4 vb = *(float4*)&Vs[k * 64 + dg * 8 + 4];
                o0.x += pv[jj] * va.x; o0.y += pv[jj] * va.y;
                o0.z += pv[jj] * va.z; o0.w += pv[jj] * va.w;
                o1.x += pv[jj] * vb.x; o1.y += pv[jj] * vb.y;
                o1.z += pv[jj] * vb.z; o1.w += pv[jj] * vb.w;
            }
        }
        float ri = rin[q];
        o0.x *= ri; o0.y *= ri; o0.z *= ri; o0.w *= ri;
        o1.x *= ri; o1.y *= ri; o1.z *= ri; o1.w *= ri;
        float* dst = o + (size_t)(qt * 32 + q) * Hn + h * HDn + dg * 8;
        *(float4*)dst = o0;
        *(float4*)(dst + 4) = o1;
    }
}

// ---------------------------------------------------------------------------
__global__ void ln_residual_kernel(const float* __restrict__ y,
                                   const float* __restrict__ g,
                                   const float* __restrict__ b,
                                   float* __restrict__ x) {
    int t = blockIdx.x;
    int tid = threadIdx.x;
    const float* row = y + (size_t)t * Hn;
    float4 v = *(const float4*)(row + tid * 4);
    float sum = v.x + v.y + v.z + v.w;
    float sq = v.x * v.x + v.y * v.y + v.z * v.z + v.w * v.w;

    __shared__ float s1[8], s2[8];
    #pragma unroll
    for (int off = 16; off > 0; off >>= 1) {
        sum += __shfl_xor_sync(0xffffffffu, sum, off);
        sq  += __shfl_xor_sync(0xffffffffu, sq, off);
    }
    if ((tid & 31) == 0) { s1[tid >> 5] = sum; s2[tid >> 5] = sq; }
    __syncthreads();
    float ts = 0.f, tq = 0.f;
    #pragma unroll
    for (int w = 0; w < 8; w++) { ts += s1[w]; tq += s2[w]; }

    float mean = ts * (1.f / Hn);
    float var = tq * (1.f / Hn) - mean * mean;
    float r = rsqrtf(var + 1e-5f);

    float4 go = *(const float4*)(g + tid * 4);
    float4 bo = *(const float4*)(b + tid * 4);
    float4 xo = *(const float4*)(x + (size_t)t * Hn + tid * 4);
    xo.x += (v.x - mean) * r * go.x + bo.x;
    xo.y += (v.y - mean) * r * go.y + bo.y;
    xo.z += (v.z - mean) * r * go.z + bo.z;
    xo.w += (v.w - mean) * r * go.w + bo.w;
    *(float4*)(x + (size_t)t * Hn + tid * 4) = xo;
}

// ---------------------------------------------------------------------------
extern "C" void kernel_launch(void* const* d_in, const int* in_sizes, int n_in,
                              void* d_out, int out_size) {
    const float* nodes     = (const float*)d_in[0];
    const float* mha_in_w  = (const float*)d_in[14];
    const float* mha_in_b  = (const float*)d_in[15];
    const float* mha_out_w = (const float*)d_in[16];
    const float* mha_out_b = (const float*)d_in[17];
    const float* mha_ln_g  = (const float*)d_in[18];
    const float* mha_ln_b  = (const float*)d_in[19];
    float* x = (float*)d_out;

    float *qkv, *o, *tmp, *part;
    cudaGetSymbolAddress((void**)&qkv,  g_qkv);
    cudaGetSymbolAddress((void**)&o,    g_o);
    cudaGetSymbolAddress((void**)&tmp,  g_tmp);
    cudaGetSymbolAddress((void**)&part, g_part);

    static bool attr_done = false;
    if (!attr_done) {
        cudaFuncSetAttribute(attn_tiled_kernel,
                             cudaFuncAttributeMaxDynamicSharedMemorySize,
                             ATTN_SMEM_BYTES);
        attr_done = true;
    }

    copy_kernel<<<(Tn * Hn + 255) / 256, 256>>>(nodes, x, Tn * Hn);

    for (int l = 0; l < 2; l++) {
        const float* Wi = mha_in_w  + (size_t)l * H3n * Hn;
        const float* bi = mha_in_b  + (size_t)l * H3n;
        const float* Wo = mha_out_w + (size_t)l * Hn * Hn;
        const float* bo = mha_out_b + (size_t)l * Hn;
        const float* lg = mha_ln_g  + (size_t)l * Hn;
        const float* lb = mha_ln_b  + (size_t)l * Hn;

        gemm_tf32_splitk<<<dim3(H3n / 64, Tn / 64, 2), 128>>>(x, Wi, part, Tn, H3n, Hn, Hn / 2);
        reduce_bias_kernel<<<(Tn * H3n / 4 + 255) / 256, 256>>>(part, bi, qkv, Tn * H3n, H3n, 2);

        attn_tiled_kernel<<<dim3(Tn / 32, NHn), 256, ATTN_SMEM_BYTES>>>(qkv, o);

        gemm_tf32_splitk<<<dim3(Hn / 64, Tn / 64, 4), 128>>>(o, Wo, part, Tn, Hn, Hn, Hn / 4);
        reduce_bias_kernel<<<(Tn * Hn / 4 + 255) / 256, 256>>>(part, bo, tmp, Tn * Hn, Hn, 4);

        ln_residual_kernel<<<Tn, 256>>>(tmp, lg, lb, x);
    }
}

// round 6
// speedup vs baseline: 5.3838x; 1.2971x over previous
#include <cuda_runtime.h>
#include <cstdint>

#define Tn 192
#define Hn 1024
#define NHn 16
#define HDn 64
#define H3n 3072

#define GKS 36   // smem row stride (words) for GEMM tiles (BK=32 wide)
#define AKS 68   // smem row stride (words) for attention Q/K tiles (64 wide)
#define PP  196  // smem row stride for score matrix P
#define ATTN_SMEM_BYTES ((32*AKS + 192*AKS + 192*64 + 32*PP + 32) * 4)

// Scratch (device globals — no allocation allowed)
__device__ __align__(16) float g_qkv[Tn * H3n];
__device__ __align__(16) float g_o[Tn * Hn];
__device__ __align__(16) float g_tmp[Tn * Hn];
__device__ __align__(16) float g_part[2 * Tn * H3n];  // covers sk2 qkv & sk4 out-proj

__device__ __forceinline__ uint32_t f2tf32(float f) {
    uint32_t u;
    asm("cvt.rna.tf32.f32 %0, %1;" : "=r"(u) : "f"(f));
    return u;
}

__device__ __forceinline__ void mma_tf32(float* c, const uint32_t* a, const uint32_t* b) {
    asm volatile(
        "mma.sync.aligned.m16n8k8.row.col.f32.tf32.tf32.f32 "
        "{%0,%1,%2,%3}, {%4,%5,%6,%7}, {%8,%9}, {%0,%1,%2,%3};"
        : "+f"(c[0]), "+f"(c[1]), "+f"(c[2]), "+f"(c[3])
        : "r"(a[0]), "r"(a[1]), "r"(a[2]), "r"(a[3]), "r"(b[0]), "r"(b[1]));
}

// ---------------------------------------------------------------------------
__global__ void copy_kernel(const float* __restrict__ src, float* __restrict__ dst, int n) {
    int i = blockIdx.x * blockDim.x + threadIdx.x;
    if (i < n) dst[i] = src[i];
}

// ---------------------------------------------------------------------------
// Split-K TF32 GEMM: P[z] = A[M,Kslice] @ B[N,Kslice]^T.
// 256 threads = 8 warps (4m x 2n), block tile 64x64, warp tile 16x32, BK=32.
__global__ void gemm_tf32_splitk(const float* __restrict__ A, const float* __restrict__ B,
                                 float* __restrict__ P, int M, int N, int K, int kps) {
    __shared__ uint32_t As[2][64][GKS];
    __shared__ uint32_t Bs[2][64][GKS];

    const int tid = threadIdx.x;
    const int wid = tid >> 5;
    const int lane = tid & 31;
    const int g = lane >> 2;
    const int t = lane & 3;

    const int bm = blockIdx.y * 64;
    const int bn = blockIdx.x * 64;
    const int wm = (wid >> 1) * 16;  // 0,16,32,48
    const int wn = (wid & 1) * 32;   // 0,32

    const int kbeg = blockIdx.z * kps;
    const int kend = kbeg + kps;

    float acc[4][4];
    #pragma unroll
    for (int ni = 0; ni < 4; ni++)
        #pragma unroll
        for (int r = 0; r < 4; r++) acc[ni][r] = 0.f;

    const int ldr = tid >> 3;        // 0..31
    const int ldc = (tid & 7) * 4;   // 0,4,...,28

    float4 pa[2], pb[2];
    #pragma unroll
    for (int i = 0; i < 2; i++) {
        int r = ldr + i * 32;
        pa[i] = *(const float4*)(A + (size_t)(bm + r) * K + kbeg + ldc);
        pb[i] = *(const float4*)(B + (size_t)(bn + r) * K + kbeg + ldc);
    }

    int buf = 0;
    #pragma unroll
    for (int i = 0; i < 2; i++) {
        int r = ldr + i * 32;
        *(uint4*)&As[0][r][ldc] = make_uint4(f2tf32(pa[i].x), f2tf32(pa[i].y),
                                             f2tf32(pa[i].z), f2tf32(pa[i].w));
        *(uint4*)&Bs[0][r][ldc] = make_uint4(f2tf32(pb[i].x), f2tf32(pb[i].y),
                                             f2tf32(pb[i].z), f2tf32(pb[i].w));
    }
    __syncthreads();

    for (int k0 = kbeg; k0 < kend; k0 += 32) {
        const bool has_next = (k0 + 32) < kend;
        if (has_next) {
            #pragma unroll
            for (int i = 0; i < 2; i++) {
                int r = ldr + i * 32;
                pa[i] = *(const float4*)(A + (size_t)(bm + r) * K + k0 + 32 + ldc);
                pb[i] = *(const float4*)(B + (size_t)(bn + r) * K + k0 + 32 + ldc);
            }
        }

        #pragma unroll
        for (int ks = 0; ks < 4; ks++) {
            const int kb = ks * 8;
            uint32_t af[4];
            af[0] = As[buf][wm + g][kb + t];
            af[1] = As[buf][wm + g + 8][kb + t];
            af[2] = As[buf][wm + g][kb + t + 4];
            af[3] = As[buf][wm + g + 8][kb + t + 4];
            uint32_t bf[4][2];
            #pragma unroll
            for (int ni = 0; ni < 4; ni++) {
                int n0 = wn + ni * 8 + g;
                bf[ni][0] = Bs[buf][n0][kb + t];
                bf[ni][1] = Bs[buf][n0][kb + t + 4];
            }
            #pragma unroll
            for (int ni = 0; ni < 4; ni++) mma_tf32(acc[ni], af, bf[ni]);
        }

        if (has_next) {
            int nb = buf ^ 1;
            #pragma unroll
            for (int i = 0; i < 2; i++) {
                int r = ldr + i * 32;
                *(uint4*)&As[nb][r][ldc] = make_uint4(f2tf32(pa[i].x), f2tf32(pa[i].y),
                                                      f2tf32(pa[i].z), f2tf32(pa[i].w));
                *(uint4*)&Bs[nb][r][ldc] = make_uint4(f2tf32(pb[i].x), f2tf32(pb[i].y),
                                                      f2tf32(pb[i].z), f2tf32(pb[i].w));
            }
            __syncthreads();
            buf = nb;
        }
    }

    float* Pz = P + (size_t)blockIdx.z * M * N;
    const int row0 = bm + wm + g;
    #pragma unroll
    for (int ni = 0; ni < 4; ni++) {
        int col0 = bn + wn + ni * 8 + 2 * t;
        Pz[(size_t)row0 * N + col0]           = acc[ni][0];
        Pz[(size_t)row0 * N + col0 + 1]       = acc[ni][1];
        Pz[(size_t)(row0 + 8) * N + col0]     = acc[ni][2];
        Pz[(size_t)(row0 + 8) * N + col0 + 1] = acc[ni][3];
    }
}

// ---------------------------------------------------------------------------
__global__ void reduce_bias_kernel(const float* __restrict__ P, const float* __restrict__ bias,
                                   float* __restrict__ C, int MN, int N, int sk) {
    int i = (blockIdx.x * blockDim.x + threadIdx.x) * 4;
    if (i >= MN) return;
    float4 s = *(const float4*)(P + i);
    for (int z = 1; z < sk; z++) {
        float4 p = *(const float4*)(P + (size_t)z * MN + i);
        s.x += p.x; s.y += p.y; s.z += p.z; s.w += p.w;
    }
    int n = i % N;
    float4 b = *(const float4*)(bias + n);
    s.x += b.x; s.y += b.y; s.z += b.z; s.w += b.w;
    *(float4*)(C + i) = s;
}

// ---------------------------------------------------------------------------
// Tiled attention: block = (32-query tile, head), 256 threads.
// Scores via tf32 mma; softmax + PV in fp32.
// Reference's additive edge bias is constant across keys (softmax over NE
// sums to 1) — a softmax invariant, omitted exactly.
__global__ void attn_tiled_kernel(const float* __restrict__ qkv, float* __restrict__ o) {
    extern __shared__ float sm[];
    uint32_t* Qs = (uint32_t*)sm;           // [32][AKS] tf32
    uint32_t* Ks = Qs + 32 * AKS;           // [192][AKS] tf32
    float* Vs  = (float*)(Ks + 192 * AKS);  // [192][64] fp32
    float* Pm  = Vs + 192 * 64;             // [32][PP]
    float* rin = Pm + 32 * PP;              // [32]

    const int qt = blockIdx.x;   // 0..5
    const int h  = blockIdx.y;   // 0..15
    const int t  = threadIdx.x;  // 0..255
    const int wid = t >> 5;
    const int lane = t & 31;
    const int g = lane >> 2;
    const int tt = lane & 3;

    // ---- stage tiles (Q,K converted to tf32; V raw fp32) ----
    #pragma unroll
    for (int i = t; i < 32 * 16; i += 256) {
        int r = i >> 4, c = (i & 15) * 4;
        float4 v = *(const float4*)&qkv[(size_t)(qt * 32 + r) * H3n + h * HDn + c];
        *(uint4*)&Qs[r * AKS + c] = make_uint4(f2tf32(v.x), f2tf32(v.y),
                                               f2tf32(v.z), f2tf32(v.w));
    }
    #pragma unroll
    for (int i = t; i < 192 * 16; i += 256) {
        int r = i >> 4, c = (i & 15) * 4;
        float4 kv = *(const float4*)&qkv[(size_t)r * H3n + Hn + h * HDn + c];
        *(uint4*)&Ks[r * AKS + c] = make_uint4(f2tf32(kv.x), f2tf32(kv.y),
                                               f2tf32(kv.z), f2tf32(kv.w));
        *(float4*)&Vs[r * 64 + c] =
            *(const float4*)&qkv[(size_t)r * H3n + 2 * Hn + h * HDn + c];
    }
    __syncthreads();

    // ---- scores via tf32 mma: warp = (mi = wid&1 m-tile, nq = wid>>1 n-group) ----
    {
        const int mi = wid & 1;        // 16-row m-tile
        const int nq = wid >> 1;       // 0..3, each covers 6 n-tiles of 8 keys
        float acc[6][4];
        #pragma unroll
        for (int j = 0; j < 6; j++)
            #pragma unroll
            for (int r = 0; r < 4; r++) acc[j][r] = 0.f;

        #pragma unroll
        for (int ks = 0; ks < 8; ks++) {
            const int kb = ks * 8;
            uint32_t af[4];
            af[0] = Qs[(mi * 16 + g) * AKS + kb + tt];
            af[1] = Qs[(mi * 16 + g + 8) * AKS + kb + tt];
            af[2] = Qs[(mi * 16 + g) * AKS + kb + tt + 4];
            af[3] = Qs[(mi * 16 + g + 8) * AKS + kb + tt + 4];
            #pragma unroll
            for (int j = 0; j < 6; j++) {
                int n0 = (nq * 6 + j) * 8 + g;
                uint32_t bf[2];
                bf[0] = Ks[n0 * AKS + kb + tt];
                bf[1] = Ks[n0 * AKS + kb + tt + 4];
                mma_tf32(acc[j], af, bf);
            }
        }
        const int row0 = mi * 16 + g;
        #pragma unroll
        for (int j = 0; j < 6; j++) {
            int col0 = (nq * 6 + j) * 8 + 2 * tt;
            Pm[row0 * PP + col0]           = acc[j][0] * 0.125f;
            Pm[row0 * PP + col0 + 1]       = acc[j][1] * 0.125f;
            Pm[(row0 + 8) * PP + col0]     = acc[j][2] * 0.125f;
            Pm[(row0 + 8) * PP + col0 + 1] = acc[j][3] * 0.125f;
        }
    }
    __syncthreads();

    // ---- softmax: warp w handles rows 4w..4w+3 ----
    {
        for (int r = wid * 4; r < wid * 4 + 4; r++) {
            float v[6];
            float mx = -1e30f;
            #pragma unroll
            for (int i = 0; i < 6; i++) {
                v[i] = Pm[r * PP + lane + 32 * i];
                mx = fmaxf(mx, v[i]);
            }
            #pragma unroll
            for (int off = 16; off > 0; off >>= 1)
                mx = fmaxf(mx, __shfl_xor_sync(0xffffffffu, mx, off));
            float sum = 0.f;
            #pragma unroll
            for (int i = 0; i < 6; i++) {
                v[i] = expf(v[i] - mx);
                sum += v[i];
                Pm[r * PP + lane + 32 * i] = v[i];
            }
            #pragma unroll
            for (int off = 16; off > 0; off >>= 1)
                sum += __shfl_xor_sync(0xffffffffu, sum, off);
            if (lane == 0) rin[r] = 1.f / sum;
        }
    }
    __syncthreads();

    // ---- PV (fp32): thread = (q = t>>3, dim-group dg = t&7 of 8 dims) ----
    {
        const int q = t >> 3;
        const int dg = t & 7;
        float4 o0 = make_float4(0.f, 0.f, 0.f, 0.f);
        float4 o1 = make_float4(0.f, 0.f, 0.f, 0.f);
        for (int kc = 0; kc < 48; kc++) {
            float4 p4 = *(float4*)&Pm[q * PP + kc * 4];
            float pv[4] = {p4.x, p4.y, p4.z, p4.w};
            #pragma unroll
            for (int jj = 0; jj < 4; jj++) {
                int k = kc * 4 + jj;
                float4 va = *(float4*)&Vs[k * 64 + dg * 8];
                float4 vb = *(float4*)&Vs[k * 64 + dg * 8 + 4];
                o0.x += pv[jj] * va.x; o0.y += pv[jj] * va.y;
                o0.z += pv[jj] * va.z; o0.w += pv[jj] * va.w;
                o1.x += pv[jj] * vb.x; o1.y += pv[jj] * vb.y;
                o1.z += pv[jj] * vb.z; o1.w += pv[jj] * vb.w;
            }
        }
        float ri = rin[q];
        o0.x *= ri; o0.y *= ri; o0.z *= ri; o0.w *= ri;
        o1.x *= ri; o1.y *= ri; o1.z *= ri; o1.w *= ri;
        float* dst = o + (size_t)(qt * 32 + q) * Hn + h * HDn + dg * 8;
        *(float4*)dst = o0;
        *(float4*)(dst + 4) = o1;
    }
}

// ---------------------------------------------------------------------------
__global__ void ln_residual_kernel(const float* __restrict__ y,
                                   const float* __restrict__ g,
                                   const float* __restrict__ b,
                                   float* __restrict__ x) {
    int t = blockIdx.x;
    int tid = threadIdx.x;
    const float* row = y + (size_t)t * Hn;
    float4 v = *(const float4*)(row + tid * 4);
    float sum = v.x + v.y + v.z + v.w;
    float sq = v.x * v.x + v.y * v.y + v.z * v.z + v.w * v.w;

    __shared__ float s1[8], s2[8];
    #pragma unroll
    for (int off = 16; off > 0; off >>= 1) {
        sum += __shfl_xor_sync(0xffffffffu, sum, off);
        sq  += __shfl_xor_sync(0xffffffffu, sq, off);
    }
    if ((tid & 31) == 0) { s1[tid >> 5] = sum; s2[tid >> 5] = sq; }
    __syncthreads();
    float ts = 0.f, tq = 0.f;
    #pragma unroll
    for (int w = 0; w < 8; w++) { ts += s1[w]; tq += s2[w]; }

    float mean = ts * (1.f / Hn);
    float var = tq * (1.f / Hn) - mean * mean;
    float r = rsqrtf(var + 1e-5f);

    float4 go = *(const float4*)(g + tid * 4);
    float4 bo = *(const float4*)(b + tid * 4);
    float4 xo = *(const float4*)(x + (size_t)t * Hn + tid * 4);
    xo.x += (v.x - mean) * r * go.x + bo.x;
    xo.y += (v.y - mean) * r * go.y + bo.y;
    xo.z += (v.z - mean) * r * go.z + bo.z;
    xo.w += (v.w - mean) * r * go.w + bo.w;
    *(float4*)(x + (size_t)t * Hn + tid * 4) = xo;
}

// ---------------------------------------------------------------------------
extern "C" void kernel_launch(void* const* d_in, const int* in_sizes, int n_in,
                              void* d_out, int out_size) {
    const float* nodes     = (const float*)d_in[0];
    const float* mha_in_w  = (const float*)d_in[14];
    const float* mha_in_b  = (const float*)d_in[15];
    const float* mha_out_w = (const float*)d_in[16];
    const float* mha_out_b = (const float*)d_in[17];
    const float* mha_ln_g  = (const float*)d_in[18];
    const float* mha_ln_b  = (const float*)d_in[19];
    float* x = (float*)d_out;

    float *qkv, *o, *tmp, *part;
    cudaGetSymbolAddress((void**)&qkv,  g_qkv);
    cudaGetSymbolAddress((void**)&o,    g_o);
    cudaGetSymbolAddress((void**)&tmp,  g_tmp);
    cudaGetSymbolAddress((void**)&part, g_part);

    static bool attr_done = false;
    if (!attr_done) {
        cudaFuncSetAttribute(attn_tiled_kernel,
                             cudaFuncAttributeMaxDynamicSharedMemorySize,
                             ATTN_SMEM_BYTES);
        attr_done = true;
    }

    copy_kernel<<<(Tn * Hn + 255) / 256, 256>>>(nodes, x, Tn * Hn);

    for (int l = 0; l < 2; l++) {
        const float* Wi = mha_in_w  + (size_t)l * H3n * Hn;
        const float* bi = mha_in_b  + (size_t)l * H3n;
        const float* Wo = mha_out_w + (size_t)l * Hn * Hn;
        const float* bo = mha_out_b + (size_t)l * Hn;
        const float* lg = mha_ln_g  + (size_t)l * Hn;
        const float* lb = mha_ln_b  + (size_t)l * Hn;

        gemm_tf32_splitk<<<dim3(H3n / 64, Tn / 64, 2), 256>>>(x, Wi, part, Tn, H3n, Hn, Hn / 2);
        reduce_bias_kernel<<<(Tn * H3n / 4 + 255) / 256, 256>>>(part, bi, qkv, Tn * H3n, H3n, 2);

        attn_tiled_kernel<<<dim3(Tn / 32, NHn), 256, ATTN_SMEM_BYTES>>>(qkv, o);

        gemm_tf32_splitk<<<dim3(Hn / 64, Tn / 64, 4), 256>>>(o, Wo, part, Tn, Hn, Hn, Hn / 4);
        reduce_bias_kernel<<<(Tn * Hn / 4 + 255) / 256, 256>>>(part, bo, tmp, Tn * Hn, Hn, 4);

        ln_residual_kernel<<<Tn, 256>>>(tmp, lg, lb, x);
    }
}

// round 7
// speedup vs baseline: 7.0034x; 1.3008x over previous
#include <cuda_runtime.h>
#include <cstdint>

#define Tn 192
#define Hn 1024
#define NHn 16
#define HDn 64
#define H3n 3072

#define GKS 36   // smem row stride (words) for GEMM tiles (BK=32 wide)
#define AKS 68   // smem row stride (words) for attention Q/K tiles (64 wide)
#define VS  196  // smem row stride for transposed V (192 keys wide)
#define PP  196  // smem row stride for score/P matrix
#define ATTN_SMEM_BYTES ((32*AKS + 192*AKS + 64*VS + 32*PP) * 4)

// Scratch (device globals — no allocation allowed)
__device__ __align__(16) float g_o[Tn * Hn];
__device__ __align__(16) float g_part[2 * Tn * H3n];  // split-K partials (sk2 qkv / sk4 out)

__device__ __forceinline__ uint32_t f2tf32(float f) {
    uint32_t u;
    asm("cvt.rna.tf32.f32 %0, %1;" : "=r"(u) : "f"(f));
    return u;
}

__device__ __forceinline__ void mma_tf32(float* c, const uint32_t* a, const uint32_t* b) {
    asm volatile(
        "mma.sync.aligned.m16n8k8.row.col.f32.tf32.tf32.f32 "
        "{%0,%1,%2,%3}, {%4,%5,%6,%7}, {%8,%9}, {%0,%1,%2,%3};"
        : "+f"(c[0]), "+f"(c[1]), "+f"(c[2]), "+f"(c[3])
        : "r"(a[0]), "r"(a[1]), "r"(a[2]), "r"(a[3]), "r"(b[0]), "r"(b[1]));
}

// ---------------------------------------------------------------------------
__global__ void copy_kernel(const float* __restrict__ src, float* __restrict__ dst, int n) {
    int i = blockIdx.x * blockDim.x + threadIdx.x;
    if (i < n) dst[i] = src[i];
}

// ---------------------------------------------------------------------------
// Split-K TF32 GEMM: P[z] = A[M,Kslice] @ B[N,Kslice]^T.
// 256 threads = 8 warps (4m x 2n), block tile 64x64, warp tile 16x32, BK=32.
__global__ void gemm_tf32_splitk(const float* __restrict__ A, const float* __restrict__ B,
                                 float* __restrict__ P, int M, int N, int K, int kps) {
    __shared__ uint32_t As[2][64][GKS];
    __shared__ uint32_t Bs[2][64][GKS];

    const int tid = threadIdx.x;
    const int wid = tid >> 5;
    const int lane = tid & 31;
    const int g = lane >> 2;
    const int t = lane & 3;

    const int bm = blockIdx.y * 64;
    const int bn = blockIdx.x * 64;
    const int wm = (wid >> 1) * 16;
    const int wn = (wid & 1) * 32;

    const int kbeg = blockIdx.z * kps;
    const int kend = kbeg + kps;

    float acc[4][4];
    #pragma unroll
    for (int ni = 0; ni < 4; ni++)
        #pragma unroll
        for (int r = 0; r < 4; r++) acc[ni][r] = 0.f;

    const int ldr = tid >> 3;
    const int ldc = (tid & 7) * 4;

    float4 pa[2], pb[2];
    #pragma unroll
    for (int i = 0; i < 2; i++) {
        int r = ldr + i * 32;
        pa[i] = *(const float4*)(A + (size_t)(bm + r) * K + kbeg + ldc);
        pb[i] = *(const float4*)(B + (size_t)(bn + r) * K + kbeg + ldc);
    }

    int buf = 0;
    #pragma unroll
    for (int i = 0; i < 2; i++) {
        int r = ldr + i * 32;
        *(uint4*)&As[0][r][ldc] = make_uint4(f2tf32(pa[i].x), f2tf32(pa[i].y),
                                             f2tf32(pa[i].z), f2tf32(pa[i].w));
        *(uint4*)&Bs[0][r][ldc] = make_uint4(f2tf32(pb[i].x), f2tf32(pb[i].y),
                                             f2tf32(pb[i].z), f2tf32(pb[i].w));
    }
    __syncthreads();

    for (int k0 = kbeg; k0 < kend; k0 += 32) {
        const bool has_next = (k0 + 32) < kend;
        if (has_next) {
            #pragma unroll
            for (int i = 0; i < 2; i++) {
                int r = ldr + i * 32;
                pa[i] = *(const float4*)(A + (size_t)(bm + r) * K + k0 + 32 + ldc);
                pb[i] = *(const float4*)(B + (size_t)(bn + r) * K + k0 + 32 + ldc);
            }
        }

        #pragma unroll
        for (int ks = 0; ks < 4; ks++) {
            const int kb = ks * 8;
            uint32_t af[4];
            af[0] = As[buf][wm + g][kb + t];
            af[1] = As[buf][wm + g + 8][kb + t];
            af[2] = As[buf][wm + g][kb + t + 4];
            af[3] = As[buf][wm + g + 8][kb + t + 4];
            uint32_t bf[4][2];
            #pragma unroll
            for (int ni = 0; ni < 4; ni++) {
                int n0 = wn + ni * 8 + g;
                bf[ni][0] = Bs[buf][n0][kb + t];
                bf[ni][1] = Bs[buf][n0][kb + t + 4];
            }
            #pragma unroll
            for (int ni = 0; ni < 4; ni++) mma_tf32(acc[ni], af, bf[ni]);
        }

        if (has_next) {
            int nb = buf ^ 1;
            #pragma unroll
            for (int i = 0; i < 2; i++) {
                int r = ldr + i * 32;
                *(uint4*)&As[nb][r][ldc] = make_uint4(f2tf32(pa[i].x), f2tf32(pa[i].y),
                                                      f2tf32(pa[i].z), f2tf32(pa[i].w));
                *(uint4*)&Bs[nb][r][ldc] = make_uint4(f2tf32(pb[i].x), f2tf32(pb[i].y),
                                                      f2tf32(pb[i].z), f2tf32(pb[i].w));
            }
            __syncthreads();
            buf = nb;
        }
    }

    float* Pz = P + (size_t)blockIdx.z * M * N;
    const int row0 = bm + wm + g;
    #pragma unroll
    for (int ni = 0; ni < 4; ni++) {
        int col0 = bn + wn + ni * 8 + 2 * t;
        Pz[(size_t)row0 * N + col0]           = acc[ni][0];
        Pz[(size_t)row0 * N + col0 + 1]       = acc[ni][1];
        Pz[(size_t)(row0 + 8) * N + col0]     = acc[ni][2];
        Pz[(size_t)(row0 + 8) * N + col0 + 1] = acc[ni][3];
    }
}

// ---------------------------------------------------------------------------
// Fused attention: consumes the qkv split-K partials (sk=2) + bias directly.
// Block = (32-query tile, head), 256 threads. Scores AND PV via tf32 mma.
// Reference's additive edge bias is constant across keys (softmax over NE
// sums to 1) — a softmax invariant, omitted exactly.
__global__ void attn_fused_kernel(const float* __restrict__ part,
                                  const float* __restrict__ bias,
                                  float* __restrict__ o) {
    extern __shared__ float sm[];
    uint32_t* Qs = (uint32_t*)sm;          // [32][AKS] tf32
    uint32_t* Ks = Qs + 32 * AKS;          // [192][AKS] tf32
    uint32_t* Vt = Ks + 192 * AKS;         // [64][VS]  tf32, transposed (dim-major)
    float* Pm = (float*)(Vt + 64 * VS);    // [32][PP]  scores, then tf32 P

    const int qt = blockIdx.x;   // 0..5
    const int h  = blockIdx.y;   // 0..15
    const int t  = threadIdx.x;  // 0..255
    const int wid = t >> 5;
    const int lane = t & 31;
    const int g = lane >> 2;
    const int tt = lane & 3;
    const int MN = Tn * H3n;

    // ---- stage tiles: sum two split-K partials + bias, convert to tf32 ----
    #pragma unroll
    for (int i = t; i < 32 * 16; i += 256) {
        int r = i >> 4, c = (i & 15) * 4;
        size_t idx = (size_t)(qt * 32 + r) * H3n + h * HDn + c;
        float4 a = *(const float4*)&part[idx];
        float4 b = *(const float4*)&part[MN + idx];
        float4 bb = *(const float4*)&bias[h * HDn + c];
        *(uint4*)&Qs[r * AKS + c] = make_uint4(
            f2tf32(a.x + b.x + bb.x), f2tf32(a.y + b.y + bb.y),
            f2tf32(a.z + b.z + bb.z), f2tf32(a.w + b.w + bb.w));
    }
    #pragma unroll
    for (int i = t; i < 192 * 16; i += 256) {
        int r = i >> 4, c = (i & 15) * 4;
        size_t idx = (size_t)r * H3n + Hn + h * HDn + c;
        float4 a = *(const float4*)&part[idx];
        float4 b = *(const float4*)&part[MN + idx];
        float4 bb = *(const float4*)&bias[Hn + h * HDn + c];
        *(uint4*)&Ks[r * AKS + c] = make_uint4(
            f2tf32(a.x + b.x + bb.x), f2tf32(a.y + b.y + bb.y),
            f2tf32(a.z + b.z + bb.z), f2tf32(a.w + b.w + bb.w));

        idx = (size_t)r * H3n + 2 * Hn + h * HDn + c;
        a = *(const float4*)&part[idx];
        b = *(const float4*)&part[MN + idx];
        bb = *(const float4*)&bias[2 * Hn + h * HDn + c];
        Vt[(c + 0) * VS + r] = f2tf32(a.x + b.x + bb.x);
        Vt[(c + 1) * VS + r] = f2tf32(a.y + b.y + bb.y);
        Vt[(c + 2) * VS + r] = f2tf32(a.z + b.z + bb.z);
        Vt[(c + 3) * VS + r] = f2tf32(a.w + b.w + bb.w);
    }
    __syncthreads();

    // ---- scores via tf32 mma ----
    {
        const int mi = wid & 1;        // 16-row m-tile
        const int nq = wid >> 1;       // 0..3, 6 n-tiles each
        float acc[6][4];
        #pragma unroll
        for (int j = 0; j < 6; j++)
            #pragma unroll
            for (int r = 0; r < 4; r++) acc[j][r] = 0.f;

        #pragma unroll
        for (int ks = 0; ks < 8; ks++) {
            const int kb = ks * 8;
            uint32_t af[4];
            af[0] = Qs[(mi * 16 + g) * AKS + kb + tt];
            af[1] = Qs[(mi * 16 + g + 8) * AKS + kb + tt];
            af[2] = Qs[(mi * 16 + g) * AKS + kb + tt + 4];
            af[3] = Qs[(mi * 16 + g + 8) * AKS + kb + tt + 4];
            #pragma unroll
            for (int j = 0; j < 6; j++) {
                int n0 = (nq * 6 + j) * 8 + g;
                uint32_t bf[2];
                bf[0] = Ks[n0 * AKS + kb + tt];
                bf[1] = Ks[n0 * AKS + kb + tt + 4];
                mma_tf32(acc[j], af, bf);
            }
        }
        const int row0 = mi * 16 + g;
        #pragma unroll
        for (int j = 0; j < 6; j++) {
            int col0 = (nq * 6 + j) * 8 + 2 * tt;
            Pm[row0 * PP + col0]           = acc[j][0] * 0.125f;
            Pm[row0 * PP + col0 + 1]       = acc[j][1] * 0.125f;
            Pm[(row0 + 8) * PP + col0]     = acc[j][2] * 0.125f;
            Pm[(row0 + 8) * PP + col0 + 1] = acc[j][3] * 0.125f;
        }
    }
    __syncthreads();

    // ---- softmax: fold 1/sum into P, store tf32 bits ----
    {
        uint32_t* Pmu = (uint32_t*)Pm;
        for (int r = wid * 4; r < wid * 4 + 4; r++) {
            float v[6];
            float mx = -1e30f;
            #pragma unroll
            for (int i = 0; i < 6; i++) {
                v[i] = Pm[r * PP + lane + 32 * i];
                mx = fmaxf(mx, v[i]);
            }
            #pragma unroll
            for (int off = 16; off > 0; off >>= 1)
                mx = fmaxf(mx, __shfl_xor_sync(0xffffffffu, mx, off));
            float sum = 0.f;
            #pragma unroll
            for (int i = 0; i < 6; i++) {
                v[i] = expf(v[i] - mx);
                sum += v[i];
            }
            #pragma unroll
            for (int off = 16; off > 0; off >>= 1)
                sum += __shfl_xor_sync(0xffffffffu, sum, off);
            float inv = 1.f / sum;
            #pragma unroll
            for (int i = 0; i < 6; i++)
                Pmu[r * PP + lane + 32 * i] = f2tf32(v[i] * inv);
        }
    }
    __syncthreads();

    // ---- PV via tf32 mma: warp = (mi, nd of 2 n-tiles = 16 dims) ----
    {
        const uint32_t* Pmu = (const uint32_t*)Pm;
        const int mi = wid & 1;
        const int nd = wid >> 1;  // 0..3
        float acc[2][4];
        #pragma unroll
        for (int jj = 0; jj < 2; jj++)
            #pragma unroll
            for (int r = 0; r < 4; r++) acc[jj][r] = 0.f;

        #pragma unroll
        for (int kt = 0; kt < 24; kt++) {
            const int kb = kt * 8;
            uint32_t af[4];
            af[0] = Pmu[(mi * 16 + g) * PP + kb + tt];
            af[1] = Pmu[(mi * 16 + g + 8) * PP + kb + tt];
            af[2] = Pmu[(mi * 16 + g) * PP + kb + tt + 4];
            af[3] = Pmu[(mi * 16 + g + 8) * PP + kb + tt + 4];
            #pragma unroll
            for (int jj = 0; jj < 2; jj++) {
                int n0 = (nd * 2 + jj) * 8 + g;
                uint32_t bf[2];
                bf[0] = Vt[n0 * VS + kb + tt];
                bf[1] = Vt[n0 * VS + kb + tt + 4];
                mma_tf32(acc[jj], af, bf);
            }
        }
        const int row0 = qt * 32 + mi * 16 + g;
        #pragma unroll
        for (int jj = 0; jj < 2; jj++) {
            int col0 = h * HDn + (nd * 2 + jj) * 8 + 2 * tt;
            o[(size_t)row0 * Hn + col0]           = acc[jj][0];
            o[(size_t)row0 * Hn + col0 + 1]       = acc[jj][1];
            o[(size_t)(row0 + 8) * Hn + col0]     = acc[jj][2];
            o[(size_t)(row0 + 8) * Hn + col0 + 1] = acc[jj][3];
        }
    }
}

// ---------------------------------------------------------------------------
// x[t,:] += LN(sum_z part[z] + bias) * g + b   (fused split-K reduce, sk=4)
__global__ void ln_residual_fused(const float* __restrict__ part,
                                  const float* __restrict__ bias,
                                  const float* __restrict__ g,
                                  const float* __restrict__ b,
                                  float* __restrict__ x) {
    const int t = blockIdx.x;
    const int tid = threadIdx.x;
    const int MN = Tn * Hn;
    const size_t base = (size_t)t * Hn + tid * 4;

    float4 v = *(const float4*)&part[base];
    #pragma unroll
    for (int z = 1; z < 4; z++) {
        float4 p = *(const float4*)&part[(size_t)z * MN + base];
        v.x += p.x; v.y += p.y; v.z += p.z; v.w += p.w;
    }
    float4 bb = *(const float4*)&bias[tid * 4];
    v.x += bb.x; v.y += bb.y; v.z += bb.z; v.w += bb.w;

    float sum = v.x + v.y + v.z + v.w;
    float sq = v.x * v.x + v.y * v.y + v.z * v.z + v.w * v.w;

    __shared__ float s1[8], s2[8];
    #pragma unroll
    for (int off = 16; off > 0; off >>= 1) {
        sum += __shfl_xor_sync(0xffffffffu, sum, off);
        sq  += __shfl_xor_sync(0xffffffffu, sq, off);
    }
    if ((tid & 31) == 0) { s1[tid >> 5] = sum; s2[tid >> 5] = sq; }
    __syncthreads();
    float ts = 0.f, tq = 0.f;
    #pragma unroll
    for (int w = 0; w < 8; w++) { ts += s1[w]; tq += s2[w]; }

    float mean = ts * (1.f / Hn);
    float var = tq * (1.f / Hn) - mean * mean;
    float r = rsqrtf(var + 1e-5f);

    float4 go = *(const float4*)&g[tid * 4];
    float4 bo = *(const float4*)&b[tid * 4];
    float4 xo = *(const float4*)&x[base];
    xo.x += (v.x - mean) * r * go.x + bo.x;
    xo.y += (v.y - mean) * r * go.y + bo.y;
    xo.z += (v.z - mean) * r * go.z + bo.z;
    xo.w += (v.w - mean) * r * go.w + bo.w;
    *(float4*)&x[base] = xo;
}

// ---------------------------------------------------------------------------
extern "C" void kernel_launch(void* const* d_in, const int* in_sizes, int n_in,
                              void* d_out, int out_size) {
    const float* nodes     = (const float*)d_in[0];
    const float* mha_in_w  = (const float*)d_in[14];
    const float* mha_in_b  = (const float*)d_in[15];
    const float* mha_out_w = (const float*)d_in[16];
    const float* mha_out_b = (const float*)d_in[17];
    const float* mha_ln_g  = (const float*)d_in[18];
    const float* mha_ln_b  = (const float*)d_in[19];
    float* x = (float*)d_out;

    float *o, *part;
    cudaGetSymbolAddress((void**)&o,    g_o);
    cudaGetSymbolAddress((void**)&part, g_part);

    static bool attr_done = false;
    if (!attr_done) {
        cudaFuncSetAttribute(attn_fused_kernel,
                             cudaFuncAttributeMaxDynamicSharedMemorySize,
                             ATTN_SMEM_BYTES);
        attr_done = true;
    }

    copy_kernel<<<(Tn * Hn + 255) / 256, 256>>>(nodes, x, Tn * Hn);

    for (int l = 0; l < 2; l++) {
        const float* Wi = mha_in_w  + (size_t)l * H3n * Hn;
        const float* bi = mha_in_b  + (size_t)l * H3n;
        const float* Wo = mha_out_w + (size_t)l * Hn * Hn;
        const float* bo = mha_out_b + (size_t)l * Hn;
        const float* lg = mha_ln_g  + (size_t)l * Hn;
        const float* lb = mha_ln_b  + (size_t)l * Hn;

        // qkv partials (sk=2): part[z] = x @ Wi^T slices
        gemm_tf32_splitk<<<dim3(H3n / 64, Tn / 64, 2), 256>>>(x, Wi, part, Tn, H3n, Hn, Hn / 2);
        // attention (consumes partials + bias directly)
        attn_fused_kernel<<<dim3(Tn / 32, NHn), 256, ATTN_SMEM_BYTES>>>(part, bi, o);
        // out-proj partials (sk=4)
        gemm_tf32_splitk<<<dim3(Hn / 64, Tn / 64, 4), 256>>>(o, Wo, part, Tn, Hn, Hn, Hn / 4);
        // fused reduce + bias + LN + residual
        ln_residual_fused<<<Tn, 256>>>(part, bo, lg, lb, x);
    }
}